// round 6
// baseline (speedup 1.0000x reference)
#include <cuda_runtime.h>
#include <cstdint>

// SJLT: out[b,p] = (1/sqrt(c)) * sum_{d,j: idx[d,j]==p} sign[d,j] * x[b,d]
//
// R3 scheme: eliminate shared-memory ATOMS (the measured 2.9 lanes/cyc wall).
//  - pack_zero: pack (idx,sign) -> uint16 (bit15 = sign), zero d_out.
//  - sjlt_scatter: 148 CTAs = 37 d-chunks x 4 batch-groups. CTA = 4 warps;
//    each warp owns a private float2 acc[4096] plane (2 batches, 32 KB).
//    RMW via plain LDS.64/FADD/STS.64; intra-warp duplicate buckets are
//    serialized exactly with __match_any_sync rank-rounds. Flush adds scaled
//    partials to d_out with global RED (coalesced).

#define NCHUNK   37
#define NGROUP   4
#define PDIM     4096
#define CDIM     8
#define FULLMASK 0xffffffffu

// 16 MB packed metadata scratch (static: allocation-free rule).
__device__ uint4 g_packed[1 << 20];

__device__ __forceinline__ unsigned pack16(int idx, int sgn) {
    // bit15 = 1 iff sgn < 0 ; bits[0:15) = idx (proj_dim <= 32768)
    return ((unsigned)idx & 0x7fffu) | (((unsigned)sgn & 0x80000000u) >> 16);
}

__global__ void pack_zero(const int4* __restrict__ idx4,
                          const int4* __restrict__ sgn4,
                          float* __restrict__ out, int D, int outN)
{
    const int d = blockIdx.x * blockDim.x + threadIdx.x;
    if (d < outN) out[d] = 0.0f;
    if (d >= D) return;
    const int4 ia = idx4[2 * d], ib = idx4[2 * d + 1];
    const int4 sa = sgn4[2 * d], sb = sgn4[2 * d + 1];
    uint4 pk;
    pk.x = pack16(ia.x, sa.x) | (pack16(ia.y, sa.y) << 16);
    pk.y = pack16(ia.z, sa.z) | (pack16(ia.w, sa.w) << 16);
    pk.z = pack16(ib.x, sb.x) | (pack16(ib.y, sb.y) << 16);
    pk.w = pack16(ib.z, sb.z) | (pack16(ib.w, sb.w) << 16);
    g_packed[d] = pk;
}

extern __shared__ float2 s_acc[];   // 4 warps * 4096 float2 = 128 KB

__global__ __launch_bounds__(128, 1)
void sjlt_scatter(const float* __restrict__ x, float* __restrict__ out,
                  int D, int chunkSz, float scale)
{
    const int chunk = blockIdx.x >> 2;          // 0..36
    const int g     = blockIdx.x & 3;           // 0..3
    const int w     = threadIdx.x >> 5;         // 0..3
    const int lane  = threadIdx.x & 31;
    float2* acc = s_acc + w * PDIM;             // warp-private plane

    // zero own plane (warps fully independent; no block sync anywhere)
    for (int i = lane; i < PDIM; i += 32) acc[i] = make_float2(0.f, 0.f);
    __syncwarp();

    const int b0 = g * 8 + w * 2;               // this warp's batch pair
    const float* x0 = x + (size_t)b0 * D;
    const float* x1 = x0 + D;

    const int d0 = chunk * chunkSz;
    const int d1 = min(D, d0 + chunkSz);
    const int nIter = (d1 - d0 + 31) >> 5;

    for (int it = 0; it < nIter; ++it) {
        const int d     = d0 + it * 32 + lane;
        const bool ok   = (d < d1);
        const int dd    = ok ? d : (d1 - 1);    // clamp; invalid lanes add 0
        const uint4 pv  = g_packed[dd];
        const unsigned vx = ok ? __float_as_uint(__ldcs(x0 + dd)) : 0u;
        const unsigned vy = ok ? __float_as_uint(__ldcs(x1 + dd)) : 0u;

        const unsigned pc[CDIM] = { pv.x & 0xffffu, pv.x >> 16,
                                    pv.y & 0xffffu, pv.y >> 16,
                                    pv.z & 0xffffu, pv.z >> 16,
                                    pv.w & 0xffffu, pv.w >> 16 };
        #pragma unroll
        for (int j = 0; j < CDIM; ++j) {
            const unsigned u    = pc[j];
            const int      p    = (int)(u & 0x7fffu);
            const unsigned flip = (u & 0x8000u) << 16;     // sign-bit flip
            const float fx = __uint_as_float(vx ^ flip);
            const float fy = __uint_as_float(vy ^ flip);

            const unsigned m = __match_any_sync(FULLMASK, p);
            if (__all_sync(FULLMASK, m == (1u << lane))) {
                // fast path (~89%): all 32 buckets distinct -> race-free RMW
                float2 t = acc[p]; t.x += fx; t.y += fy; acc[p] = t;
            } else {
                // duplicates: serialize equal-p lanes by rank (exact)
                const unsigned rank = __popc(m & ((1u << lane) - 1u));
                const unsigned maxr = __reduce_max_sync(FULLMASK, rank);
                for (unsigned r = 0; r <= maxr; ++r) {
                    if (rank == r) {
                        float2 t = acc[p]; t.x += fx; t.y += fy; acc[p] = t;
                    }
                }
            }
        }
    }
    __syncwarp();

    // flush: scaled partial -> out via global RED (coalesced, 37 adders/slot)
    float* o0 = out + (size_t)b0 * PDIM;
    for (int i = lane; i < PDIM; i += 32) {
        const float2 t = acc[i];
        atomicAdd(o0 + i,        t.x * scale);
        atomicAdd(o0 + PDIM + i, t.y * scale);
    }
}

extern "C" void kernel_launch(void* const* d_in, const int* in_sizes, int n_in,
                              void* d_out, int out_size)
{
    const float* x    = (const float*)d_in[0];
    const int4*  idx4 = (const int4*) d_in[1];
    const int4*  sgn4 = (const int4*) d_in[2];

    const int D       = in_sizes[1] / CDIM;            // 1,000,000
    const int chunkSz = (D + NCHUNK - 1) / NCHUNK;     // 27,028
    const float scale = 0.35355339059327373f;          // 1/sqrt(8)

    cudaFuncSetAttribute(sjlt_scatter,
                         cudaFuncAttributeMaxDynamicSharedMemorySize,
                         NGROUP * PDIM * (int)sizeof(float2));

    pack_zero<<<(D + 255) / 256, 256>>>(idx4, sgn4, (float*)d_out, D, out_size);

    sjlt_scatter<<<NCHUNK * NGROUP, 128, NGROUP * PDIM * sizeof(float2)>>>(
        x, (float*)d_out, D, chunkSz, scale);
}

// round 10
// speedup vs baseline: 1.9185x; 1.9185x over previous
#include <cuda_runtime.h>
#include <cstdint>

// SJLT: out[b,p] = (1/sqrt(c)) * sum_{d,j: idx[d,j]==p} sign[d,j] * x[b,d]
//
// R5: non-atomic warp-private RMW, latency-engineered.
//  - pack:     (idx,sign) -> uint16 (bit15 = sign), 16 MB scratch.
//  - scatter:  1024 warp-tasks = 16 batch-pairs x 64 d-chunks on 147 CTAs.
//    CTA = 7 warps, each warp owns a private float2 acc[4096] plane (32 KB,
//    224 KB/CTA). RMW = LDS.64/FADD/STS.64 (no ATOMS). All match_any/popc/
//    reduce_max hoisted before the RMW chain; duplicates resolved exactly
//    via rank rounds guarded by the warp-uniform maxr (no divergence in the
//    common path). Next iteration's loads prefetched above the chain.
//  - reduce:   sum 64 chunk-partials, scale, write out.

#define PDIM     4096
#define CDIM     8
#define NCHUNK   64
#define NBP      16          // batch pairs (32 batches / 2)
#define WPB      7           // warps per CTA
#define FULLMASK 0xffffffffu

// static scratch (allocation-free rule)
__device__ uint4  g_packed[1 << 20];                          // 16 MB
__device__ float2 g_partial[(size_t)NCHUNK * NBP * PDIM];     // 33.5 MB

__device__ __forceinline__ unsigned pack16(int idx, int sgn) {
    return ((unsigned)idx & 0x7fffu) | (((unsigned)sgn & 0x80000000u) >> 16);
}

__global__ void sjlt_pack(const int4* __restrict__ idx4,
                          const int4* __restrict__ sgn4, int D)
{
    const int d = blockIdx.x * blockDim.x + threadIdx.x;
    if (d >= D) return;
    const int4 ia = idx4[2 * d], ib = idx4[2 * d + 1];
    const int4 sa = sgn4[2 * d], sb = sgn4[2 * d + 1];
    uint4 pk;
    pk.x = pack16(ia.x, sa.x) | (pack16(ia.y, sa.y) << 16);
    pk.y = pack16(ia.z, sa.z) | (pack16(ia.w, sa.w) << 16);
    pk.z = pack16(ib.x, sb.x) | (pack16(ib.y, sb.y) << 16);
    pk.w = pack16(ib.z, sb.z) | (pack16(ib.w, sb.w) << 16);
    g_packed[d] = pk;
}

extern __shared__ float2 s_acc[];   // WPB * PDIM float2 = 224 KB

__global__ __launch_bounds__(WPB * 32, 1)
void sjlt_scatter(const float* __restrict__ x, int D, int chunkSz)
{
    const int wid  = threadIdx.x >> 5;
    const int lane = threadIdx.x & 31;
    const int W    = blockIdx.x * WPB + wid;        // warp task id
    if (W >= NBP * NCHUNK) return;                  // warps are independent
    const int bp    = W & (NBP - 1);
    const int chunk = W >> 4;

    float2* acc = s_acc + wid * PDIM;               // warp-private plane
    for (int i = lane; i < PDIM; i += 32) acc[i] = make_float2(0.f, 0.f);
    __syncwarp();

    const float* x0 = x + (size_t)(2 * bp) * D;
    const float* x1 = x0 + D;
    const int d0 = chunk * chunkSz;
    const int d1 = min(D, d0 + chunkSz);
    const int nIter = (d1 - d0 + 31) >> 5;
    const unsigned lmask_lt = (1u << lane) - 1u;

    // software-pipelined loads: fetch iter 0
    int dc0 = min(d0 + lane, d1 - 1);
    uint4    pv = g_packed[dc0];
    unsigned vx = (d0 + lane < d1) ? __float_as_uint(__ldcs(x0 + dc0)) : 0u;
    unsigned vy = (d0 + lane < d1) ? __float_as_uint(__ldcs(x1 + dc0)) : 0u;

    for (int it = 0; it < nIter; ++it) {
        const uint4    cpv = pv;
        const unsigned cvx = vx, cvy = vy;

        // prefetch iter it+1 above the RMW chain
        if (it + 1 < nIter) {
            const int dn = d0 + (it + 1) * 32 + lane;
            const int dc = min(dn, d1 - 1);
            pv = g_packed[dc];
            const bool okn = (dn < d1);
            vx = okn ? __float_as_uint(__ldcs(x0 + dc)) : 0u;
            vy = okn ? __float_as_uint(__ldcs(x1 + dc)) : 0u;
        }

        const unsigned pc[CDIM] = { cpv.x & 0xffffu, cpv.x >> 16,
                                    cpv.y & 0xffffu, cpv.y >> 16,
                                    cpv.z & 0xffffu, cpv.z >> 16,
                                    cpv.w & 0xffffu, cpv.w >> 16 };
        int      p[CDIM];
        unsigned fl[CDIM], rank[CDIM], maxr[CDIM];

        // prep phase: all warp-collectives, pipelined, outside the RMW chain
        #pragma unroll
        for (int j = 0; j < CDIM; ++j) {
            p[j]  = (int)(pc[j] & 0x7fffu);
            fl[j] = (pc[j] & 0x8000u) << 16;            // fp32 sign-bit flip
            const unsigned m = __match_any_sync(FULLMASK, p[j]);
            rank[j] = __popc(m & lmask_lt);
            maxr[j] = __reduce_max_sync(FULLMASK, rank[j]);   // warp-uniform
        }

        // RMW chain: common case has no divergence and no votes
        #pragma unroll
        for (int j = 0; j < CDIM; ++j) {
            const float fx = __uint_as_float(cvx ^ fl[j]);
            const float fy = __uint_as_float(cvy ^ fl[j]);
            if (maxr[j] == 0u) {                         // warp-uniform branch
                float2 t = acc[p[j]];
                t.x += fx; t.y += fy;
                acc[p[j]] = t;
            } else {                                     // exact rank rounds
                for (unsigned r = 0; r <= maxr[j]; ++r) {
                    if (rank[j] == r) {
                        float2 t = acc[p[j]];
                        t.x += fx; t.y += fy;
                        acc[p[j]] = t;
                    }
                }
            }
        }
    }
    __syncwarp();

    // flush partial plane: plain coalesced STG, unique (chunk,bp) owner
    float2* dst = g_partial + ((size_t)chunk * NBP + bp) * PDIM;
    for (int i = lane; i < PDIM; i += 32) dst[i] = acc[i];
}

__global__ void sjlt_reduce(float* __restrict__ out, float scale)
{
    const int t  = blockIdx.x * blockDim.x + threadIdx.x;   // 0..65535
    const int bp = t >> 12;
    const int p  = t & (PDIM - 1);
    const float2* src = g_partial + (size_t)bp * PDIM + p;

    float sx[4] = {0.f, 0.f, 0.f, 0.f};
    float sy[4] = {0.f, 0.f, 0.f, 0.f};
    #pragma unroll
    for (int c = 0; c < NCHUNK; ++c) {
        const float2 v = src[(size_t)c * (NBP * PDIM)];
        sx[c & 3] += v.x;
        sy[c & 3] += v.y;
    }
    const float rx = (sx[0] + sx[1]) + (sx[2] + sx[3]);
    const float ry = (sy[0] + sy[1]) + (sy[2] + sy[3]);
    out[(size_t)(2 * bp) * PDIM + p]     = rx * scale;
    out[(size_t)(2 * bp + 1) * PDIM + p] = ry * scale;
}

extern "C" void kernel_launch(void* const* d_in, const int* in_sizes, int n_in,
                              void* d_out, int out_size)
{
    const float* x    = (const float*)d_in[0];
    const int4*  idx4 = (const int4*) d_in[1];
    const int4*  sgn4 = (const int4*) d_in[2];

    const int D       = in_sizes[1] / CDIM;               // 1,000,000
    const int chunkSz = (D + NCHUNK - 1) / NCHUNK;        // 15,625
    const float scale = 0.35355339059327373f;             // 1/sqrt(8)

    cudaFuncSetAttribute(sjlt_scatter,
                         cudaFuncAttributeMaxDynamicSharedMemorySize,
                         WPB * PDIM * (int)sizeof(float2));   // 229376 B

    sjlt_pack<<<(D + 255) / 256, 256>>>(idx4, sgn4, D);

    const int nTasks = NBP * NCHUNK;                      // 1024
    const int grid   = (nTasks + WPB - 1) / WPB;          // 147
    sjlt_scatter<<<grid, WPB * 32, WPB * PDIM * sizeof(float2)>>>(x, D, chunkSz);

    sjlt_reduce<<<(NBP * PDIM) / 256, 256>>>((float*)d_out, scale);
}

// round 11
// speedup vs baseline: 2.8437x; 1.4822x over previous
#include <cuda_runtime.h>
#include <cstdint>

// SJLT: out[b,p] = (1/sqrt(c)) * sum_{d,j: idx[d,j]==p} sign[d,j] * x[b,d]
//
// R6: lane = batch. Stage x-tile transposed in SMEM; each (d,j) event is ONE
// conflict-free warp-atomic (addresses p*32+lane) covering all 32 batches.
// Grid = 37 d-chunks x 4 proj-segments (1024 p each). Partials -> scratch,
// tiny transpose-reduce writes out.

#define PDIM    4096
#define CDIM    8
#define NCHUNK  37
#define NSEG    4
#define SEGP    1024          // p's per segment
#define BDIM    512           // 16 warps
#define DTILE   512           // d's staged per tile
#define XSTR    513           // padded row stride (conflict-free column reads)

// static scratch (allocation-free rule)
__device__ uint4 g_packed[1 << 20];                              // 16 MB
__device__ float g_partial[(size_t)NCHUNK * PDIM * 32];          // 19.4 MB

__device__ __forceinline__ unsigned pack16(int idx, int sgn) {
    // bits[0:12) = p, bit15 = sign<0
    return ((unsigned)idx & 0x7fffu) | (((unsigned)sgn & 0x80000000u) >> 16);
}

__global__ void sjlt_pack(const int4* __restrict__ idx4,
                          const int4* __restrict__ sgn4, int D)
{
    const int d = blockIdx.x * blockDim.x + threadIdx.x;
    if (d >= D) return;
    const int4 ia = idx4[2 * d], ib = idx4[2 * d + 1];
    const int4 sa = sgn4[2 * d], sb = sgn4[2 * d + 1];
    uint4 pk;
    pk.x = pack16(ia.x, sa.x) | (pack16(ia.y, sa.y) << 16);
    pk.y = pack16(ia.z, sa.z) | (pack16(ia.w, sa.w) << 16);
    pk.z = pack16(ib.x, sb.x) | (pack16(ib.y, sb.y) << 16);
    pk.w = pack16(ib.z, sb.z) | (pack16(ib.w, sb.w) << 16);
    g_packed[d] = pk;
}

extern __shared__ float s_mem[];
// layout: s_acc[SEGP*32] | s_x[32*XSTR] | s_meta[DTILE] (uint4)

__global__ __launch_bounds__(BDIM, 1)
void sjlt_scatter(const float* __restrict__ x, int D, int chunkSz)
{
    float* s_acc = s_mem;                          // 131072 B
    float* s_x   = s_acc + SEGP * 32;              //  65664 B
    uint4* s_meta = (uint4*)(s_x + 32 * XSTR);     //   8192 B

    const int chunk = blockIdx.x >> 2;
    const unsigned seg = blockIdx.x & 3u;
    const int tid  = threadIdx.x;
    const int w    = tid >> 5;
    const int lane = tid & 31;

    for (int i = tid; i < SEGP * 32; i += BDIM) s_acc[i] = 0.0f;
    __syncthreads();

    const int d0 = chunk * chunkSz;
    const int d1 = min(D, d0 + chunkSz);

    for (int dt = d0; dt < d1; dt += DTILE) {
        const int rem = min(DTILE, d1 - dt);       // always a multiple of 4
        const int r4  = rem >> 2;

        // stage x[b][dt..dt+rem) into padded SMEM rows (coalesced LDG.128)
        for (int b = w; b < 32; b += 16) {
            const float4* src = (const float4*)(x + (size_t)b * D + dt);
            float* dst = s_x + b * XSTR;
            for (int c4 = lane; c4 < r4; c4 += 32) {
                const float4 v = src[c4];
                dst[4 * c4 + 0] = v.x; dst[4 * c4 + 1] = v.y;
                dst[4 * c4 + 2] = v.z; dst[4 * c4 + 3] = v.w;
            }
        }
        if (tid < rem) s_meta[tid] = g_packed[dt + tid];
        __syncthreads();

        // each warp owns 32 consecutive d's of the tile
        const int kmax = min(32, rem - (w << 5));
        for (int k = 0; k < kmax; ++k) {
            const int col = (w << 5) + k;
            const uint4 pv = s_meta[col];                     // broadcast LDS
            const unsigned xb =
                __float_as_uint(s_x[lane * XSTR + col]);      // conflict-free
            const unsigned f[CDIM] = { pv.x & 0xffffu, pv.x >> 16,
                                       pv.y & 0xffffu, pv.y >> 16,
                                       pv.z & 0xffffu, pv.z >> 16,
                                       pv.w & 0xffffu, pv.w >> 16 };
            #pragma unroll
            for (int j = 0; j < CDIM; ++j) {
                const unsigned u = f[j];
                if (((u >> 10) & 3u) == seg) {                // warp-uniform
                    // conflict-free banks: addr = (p&1023)*32 + lane
                    atomicAdd(s_acc + ((u & 1023u) << 5) + lane,
                              __uint_as_float(xb ^ ((u & 0x8000u) << 16)));
                }
            }
        }
        __syncthreads();
    }

    // flush partial plane: unique (chunk,seg) owner, coalesced STG
    float* dst = g_partial + ((size_t)chunk * PDIM + seg * SEGP) * 32;
    for (int i = tid; i < SEGP * 32; i += BDIM) dst[i] = s_acc[i];
}

__global__ __launch_bounds__(1024)
void sjlt_reduce(float* __restrict__ out, float scale)
{
    __shared__ float s_r[32 * 33];
    const int tid = threadIdx.x;
    const int p0  = blockIdx.x * 32;

    // coalesced reads: consecutive tid -> consecutive (p, b) addresses
    const int pp = tid >> 5, b = tid & 31;
    const float* src = g_partial + ((size_t)(p0 + pp)) * 32 + b;
    float s = 0.0f;
    #pragma unroll
    for (int c = 0; c < NCHUNK; ++c)
        s += src[(size_t)c * PDIM * 32];
    s_r[pp * 33 + b] = s * scale;
    __syncthreads();

    // transposed write: lanes sweep p -> coalesced STG
    const int b2 = tid >> 5, p2 = tid & 31;
    out[(size_t)b2 * PDIM + p0 + p2] = s_r[p2 * 33 + b2];
}

extern "C" void kernel_launch(void* const* d_in, const int* in_sizes, int n_in,
                              void* d_out, int out_size)
{
    const float* x    = (const float*)d_in[0];
    const int4*  idx4 = (const int4*) d_in[1];
    const int4*  sgn4 = (const int4*) d_in[2];

    const int D       = in_sizes[1] / CDIM;               // 1,000,000
    const int chunkSz = (D + NCHUNK - 1) / NCHUNK;        // 27,028 (mult of 4)
    const float scale = 0.35355339059327373f;             // 1/sqrt(8)

    const int smemB = (SEGP * 32 + 32 * XSTR) * (int)sizeof(float)
                    + DTILE * (int)sizeof(uint4);         // 204,928 B
    cudaFuncSetAttribute(sjlt_scatter,
                         cudaFuncAttributeMaxDynamicSharedMemorySize, smemB);

    sjlt_pack<<<(D + 255) / 256, 256>>>(idx4, sgn4, D);
    sjlt_scatter<<<NCHUNK * NSEG, BDIM, smemB>>>(x, D, chunkSz);
    sjlt_reduce<<<PDIM / 32, 1024>>>((float*)d_out, scale);
}

// round 13
// speedup vs baseline: 3.8236x; 1.3446x over previous
#include <cuda_runtime.h>
#include <cstdint>

// SJLT: out[b,p] = (1/sqrt(c)) * sum_{d,j: idx[d,j]==p} sign[d,j] * x[b,d]
//
// R7: bypass the SMEM atomic unit entirely.
//   zero      : reset bin cursors + out.
//   transpose : xT[d][b] (128 B per d) so 32 batch values = one LDG.128.
//   pack      : event word (d<<7 | sign<<6 | p&63) binned by p>>6 into 64
//               per-bin global arrays (SMEM staging, bulk cursor flush).
//   scatter   : 148 CTAs = 37 slices x 4 bin-quads; 16 warps/CTA, warp w
//               EXCLUSIVELY owns bin seg*16+w -> private padded acc plane
//               (64p x 32b). RMW = conflict-free LDS/FADD/STS, no atomics,
//               no warp collectives except one SHFL broadcast per event.
//               Flush: transposed conflict-free LDS + coalesced global RED.

#define PDIM     4096
#define CDIM     8
#define NBIN     64
#define BINP     64            // p's per bin
#define MAXBIN   131072        // slots per bin (mean 125k, +17 sigma)
#define NSLICE   37
#define SWPB     16            // scatter warps per CTA
#define ACCSTR   33            // padded row stride (floats)
#define ACCSZ    (BINP * ACCSTR)
#define PCAP     384           // pack SMEM slots per bin
#define PACKD    2048          // d's per pack CTA
#define FULLMASK 0xffffffffu

// static scratch (allocation-free rule)
__device__ float    g_xT[(size_t)32 * 1000000];            // 128 MB
__device__ unsigned g_events[(size_t)NBIN * MAXBIN];       //  32 MB
__device__ int      g_cursor[NBIN];

__global__ void sjlt_zero(float* __restrict__ out, int outN)
{
    const int i = blockIdx.x * blockDim.x + threadIdx.x;
    if (i < outN) out[i] = 0.0f;
    if (i < NBIN) g_cursor[i] = 0;
}

// ---- transpose: x[b][d] -> xT[d][b], tiles of 64 d x 32 b ----
__global__ __launch_bounds__(256)
void sjlt_transpose(const float* __restrict__ x, int D)
{
    __shared__ float tile[64 * 33];
    const int d0   = blockIdx.x * 64;
    const int wid  = threadIdx.x >> 5;
    const int lane = threadIdx.x & 31;

    for (int b = wid; b < 32; b += 8) {
        const float* src = x + (size_t)b * D + d0;
        tile[lane * 33 + b]        = src[lane];
        tile[(lane + 32) * 33 + b] = src[lane + 32];
    }
    __syncthreads();
    for (int dd = wid; dd < 64; dd += 8)
        g_xT[(size_t)(d0 + dd) * 32 + lane] = tile[dd * 33 + lane];
}

// ---- pack: bin events by p>>6 ----
extern __shared__ unsigned p_smem[];   // s_buf[NBIN*PCAP] | s_cnt[NBIN]

__global__ __launch_bounds__(256)
void sjlt_pack(const int4* __restrict__ idx4,
               const int4* __restrict__ sgn4, int D)
{
    unsigned* s_buf = p_smem;
    int*      s_cnt = (int*)(p_smem + NBIN * PCAP);
    const int tid  = threadIdx.x;
    const int wid  = tid >> 5;
    const int lane = tid & 31;

    if (tid < NBIN) s_cnt[tid] = 0;
    __syncthreads();

    const int dBase = blockIdx.x * PACKD;
    for (int r = 0; r < PACKD / 256; ++r) {
        const int d = dBase + r * 256 + tid;
        if (d >= D) break;
        const int4 ia = idx4[2 * d], ib = idx4[2 * d + 1];
        const int4 sa = sgn4[2 * d], sb = sgn4[2 * d + 1];
        const int  pj[CDIM] = {ia.x, ia.y, ia.z, ia.w, ib.x, ib.y, ib.z, ib.w};
        const int  sj[CDIM] = {sa.x, sa.y, sa.z, sa.w, sb.x, sb.y, sb.z, sb.w};
        #pragma unroll
        for (int j = 0; j < CDIM; ++j) {
            const unsigned p = (unsigned)pj[j];
            const unsigned u = ((unsigned)d << 7)
                             | ((sj[j] < 0) ? 0x40u : 0u)
                             | (p & 63u);
            const int bin  = (int)(p >> 6);
            const int slot = atomicAdd(&s_cnt[bin], 1);
            if (slot < PCAP) {
                s_buf[bin * PCAP + slot] = u;
            } else {                                  // ~never (+8 sigma)
                const int gs = atomicAdd(&g_cursor[bin], 1);
                g_events[(size_t)bin * MAXBIN + gs] = u;
            }
        }
    }
    __syncthreads();

    // bulk flush: one warp per bin, contiguous reservation
    for (int bin = wid; bin < NBIN; bin += 8) {
        const int cnt = min(s_cnt[bin], PCAP);
        int base = 0;
        if (lane == 0) base = atomicAdd(&g_cursor[bin], cnt);
        base = __shfl_sync(FULLMASK, base, 0);
        unsigned* dst = g_events + (size_t)bin * MAXBIN + base;
        const unsigned* src = s_buf + bin * PCAP;
        for (int i = lane; i < cnt; i += 32) dst[i] = src[i];
    }
}

// ---- scatter: warp-exclusive bins, LDS/STS RMW ----
extern __shared__ float s_acc[];   // SWPB * ACCSZ floats = 135168 B

__global__ __launch_bounds__(SWPB * 32, 1)
void sjlt_scatter(float* __restrict__ out, float scale)
{
    const int slice = blockIdx.x >> 2;
    const int seg   = blockIdx.x & 3;
    const int wid   = threadIdx.x >> 5;
    const int lane  = threadIdx.x & 31;
    const int bin   = seg * SWPB + wid;          // exclusive owner
    float* acc = s_acc + wid * ACCSZ;

    for (int i = lane; i < ACCSZ; i += 32) acc[i] = 0.0f;
    __syncwarp();

    const int cnt = g_cursor[bin];
    const int i0  = (int)((long long)cnt * slice / NSLICE);
    const int i1  = (int)((long long)cnt * (slice + 1) / NSLICE);
    const unsigned* ev = g_events + (size_t)bin * MAXBIN;
    const float* xT = g_xT;

    for (int base = i0; base < i1; base += 32) {
        const int  idx = base + lane;
        const unsigned evw = (idx < i1) ? __ldcs(ev + idx) : 0u;
        const int  rem = min(32, i1 - base);

        for (int g8 = 0; g8 < 4; ++g8) {
            unsigned u[8], xv[8];
            #pragma unroll
            for (int q = 0; q < 8; ++q) {
                const int k = g8 * 8 + q;
                u[q] = __shfl_sync(FULLMASK, evw, k);
                xv[q] = (k < rem)
                    ? __float_as_uint(__ldg(xT + (size_t)(u[q] >> 7) * 32 + lane))
                    : 0u;
            }
            #pragma unroll
            for (int q = 0; q < 8; ++q) {
                const int k = g8 * 8 + q;
                if (k < rem) {
                    const unsigned flip = (u[q] & 0x40u) << 25;   // sign bit
                    float* a = acc + (u[q] & 63u) * ACCSTR + lane;
                    *a += __uint_as_float(xv[q] ^ flip);          // LDS+FADD+STS
                }
            }
        }
    }
    __syncwarp();

    // flush: transposed conflict-free reads, coalesced RED to out
    const int p0 = bin * BINP;
    for (int b = 0; b < 32; ++b) {
        #pragma unroll
        for (int h = 0; h < 2; ++h) {
            const int p6 = lane + 32 * h;
            const float v = acc[p6 * ACCSTR + b];                 // bank-clean
            atomicAdd(out + (size_t)b * PDIM + p0 + p6, v * scale);
        }
    }
}

extern "C" void kernel_launch(void* const* d_in, const int* in_sizes, int n_in,
                              void* d_out, int out_size)
{
    const float* x    = (const float*)d_in[0];
    const int4*  idx4 = (const int4*) d_in[1];
    const int4*  sgn4 = (const int4*) d_in[2];

    const int D       = in_sizes[1] / CDIM;            // 1,000,000
    const float scale = 0.35355339059327373f;          // 1/sqrt(8)

    const int packSm = NBIN * PCAP * 4 + NBIN * 4;               // 98,560 B
    const int scatSm = SWPB * ACCSZ * (int)sizeof(float);        // 135,168 B
    cudaFuncSetAttribute(sjlt_pack,
                         cudaFuncAttributeMaxDynamicSharedMemorySize, packSm);
    cudaFuncSetAttribute(sjlt_scatter,
                         cudaFuncAttributeMaxDynamicSharedMemorySize, scatSm);

    sjlt_zero<<<(out_size + 255) / 256, 256>>>((float*)d_out, out_size);
    sjlt_transpose<<<D / 64, 256>>>(x, D);
    sjlt_pack<<<(D + PACKD - 1) / PACKD, 256, packSm>>>(idx4, sgn4, D);
    sjlt_scatter<<<NSLICE * 4, SWPB * 32, scatSm>>>((float*)d_out, scale);
}

// round 15
// speedup vs baseline: 5.9620x; 1.5593x over previous
#include <cuda_runtime.h>
#include <cstdint>

// SJLT: out[b,p] = (1/sqrt(c)) * sum_{d,j: idx[d,j]==p} sign[d,j] * x[b,d]
//
// R8: event-list scatter, throughput-engineered.
//   event u32 = d<<8 | sign<<7 | row(7b), row = p&63 (row 64 = pad sink)
//   xT byte offset = (u>>1) & ~127 ; acc row = u & 0x7F  -> no predication.
//   scatter: 148 CTAs = 37 slices x 4 bin-quads, warp-exclusive bin planes
//   (65 x 33 floats, conflict-free), double-buffered 8-event groups.

#define PDIM     4096
#define CDIM     8
#define NBIN     64
#define MAXBIN   131072
#define NSLICE   37
#define SWPB     16
#define ACCROWS  65
#define ACCSTR   33
#define ACCSZ    (ACCROWS * ACCSTR)        // 2145 floats/warp
#define PCAP     384
#define PACKD    2048
#define PADEV    64u
#define FULLMASK 0xffffffffu

// static scratch (allocation-free rule)
__device__ float    g_xT[(size_t)32 * 1000000];                  // 128 MB
__device__ unsigned g_events[(size_t)NBIN * MAXBIN];             //  32 MB
__device__ float    g_partial[(size_t)NSLICE * PDIM * 32];       //19.4 MB
__device__ int      g_cursor[NBIN];

__global__ void sjlt_zero()
{
    if (threadIdx.x < NBIN) g_cursor[threadIdx.x] = 0;
}

// ---- transpose: x[b][d] -> xT[d][b] ----
__global__ __launch_bounds__(256)
void sjlt_transpose(const float* __restrict__ x, int D)
{
    __shared__ float tile[64 * 33];
    const int d0   = blockIdx.x * 64;
    const int wid  = threadIdx.x >> 5;
    const int lane = threadIdx.x & 31;

    for (int b = wid; b < 32; b += 8) {
        const float* src = x + (size_t)b * D + d0;
        tile[lane * 33 + b]        = src[lane];
        tile[(lane + 32) * 33 + b] = src[lane + 32];
    }
    __syncthreads();
    for (int dd = wid; dd < 64; dd += 8)
        g_xT[(size_t)(d0 + dd) * 32 + lane] = tile[dd * 33 + lane];
}

// ---- pack: bin events by p>>6 ----
extern __shared__ unsigned p_smem[];   // s_buf[NBIN*PCAP] | s_cnt[NBIN]

__global__ __launch_bounds__(256)
void sjlt_pack(const int4* __restrict__ idx4,
               const int4* __restrict__ sgn4, int D)
{
    unsigned* s_buf = p_smem;
    int*      s_cnt = (int*)(p_smem + NBIN * PCAP);
    const int tid  = threadIdx.x;
    const int wid  = tid >> 5;
    const int lane = tid & 31;

    if (tid < NBIN) s_cnt[tid] = 0;
    __syncthreads();

    const int dBase = blockIdx.x * PACKD;
    for (int r = 0; r < PACKD / 256; ++r) {
        const int d = dBase + r * 256 + tid;
        if (d >= D) break;
        const int4 ia = idx4[2 * d], ib = idx4[2 * d + 1];
        const int4 sa = sgn4[2 * d], sb = sgn4[2 * d + 1];
        const int  pj[CDIM] = {ia.x, ia.y, ia.z, ia.w, ib.x, ib.y, ib.z, ib.w};
        const int  sj[CDIM] = {sa.x, sa.y, sa.z, sa.w, sb.x, sb.y, sb.z, sb.w};
        #pragma unroll
        for (int j = 0; j < CDIM; ++j) {
            const unsigned p = (unsigned)pj[j];
            const unsigned u = ((unsigned)d << 8)
                             | ((sj[j] < 0) ? 0x80u : 0u)
                             | (p & 63u);
            const int bin  = (int)(p >> 6);
            const int slot = atomicAdd(&s_cnt[bin], 1);
            if (slot < PCAP) {
                s_buf[bin * PCAP + slot] = u;
            } else {                                  // rare overflow
                const int gs = atomicAdd(&g_cursor[bin], 1);
                g_events[(size_t)bin * MAXBIN + gs] = u;
            }
        }
    }
    __syncthreads();

    for (int bin = wid; bin < NBIN; bin += 8) {
        const int cnt = min(s_cnt[bin], PCAP);
        int base = 0;
        if (lane == 0) base = atomicAdd(&g_cursor[bin], cnt);
        base = __shfl_sync(FULLMASK, base, 0);
        unsigned* dst = g_events + (size_t)bin * MAXBIN + base;
        const unsigned* src = s_buf + bin * PCAP;
        for (int i = lane; i < cnt; i += 32) dst[i] = src[i];
    }
}

// ---- scatter helpers ----
__device__ __forceinline__ void grp_load(unsigned evw, int g, const char* xbase,
                                         unsigned* u, unsigned* xv)
{
    #pragma unroll
    for (int q = 0; q < 8; ++q) {
        u[q]  = __shfl_sync(FULLMASK, evw, g * 8 + q);
        xv[q] = __float_as_uint(
            __ldg((const float*)(xbase + ((u[q] >> 1) & 0xFFFFFF80u))));
    }
}

__device__ __forceinline__ void grp_rmw(float* accl, const unsigned* u,
                                        const unsigned* xv)
{
    #pragma unroll
    for (int q = 0; q < 8; ++q) {
        const unsigned flip = (u[q] & 0x80u) << 24;
        accl[(u[q] & 0x7Fu) * ACCSTR] += __uint_as_float(xv[q] ^ flip);
    }
}

extern __shared__ float s_acc[];   // SWPB * ACCSZ = 137280 B

__global__ __launch_bounds__(SWPB * 32, 1)
void sjlt_scatter()
{
    const int slice = blockIdx.x >> 2;
    const int seg   = blockIdx.x & 3;
    const int wid   = threadIdx.x >> 5;
    const int lane  = threadIdx.x & 31;
    const int bin   = seg * SWPB + wid;          // exclusive owner
    float* acc  = s_acc + wid * ACCSZ;
    float* accl = acc + lane;

    for (int i = lane; i < ACCSZ; i += 32) acc[i] = 0.0f;
    __syncwarp();

    const int cnt = min(g_cursor[bin], MAXBIN);
    const int i0  = (int)((long long)cnt * slice / NSLICE);
    const int i1  = (int)((long long)cnt * (slice + 1) / NSLICE);
    const unsigned* ev = g_events + (size_t)bin * MAXBIN;
    const char* xbase  = (const char*)g_xT + (lane << 2);

    const int nBatch = (i1 - i0 + 31) >> 5;
    unsigned evw = (i0 + lane < i1) ? __ldcs(ev + i0 + lane) : PADEV;

    unsigned uA[8], xA[8], uB[8], xB[8];
    for (int bt = 0; bt < nBatch; ++bt) {
        // prefetch next batch's event words
        unsigned evn = PADEV;
        const int nb = i0 + (bt + 1) * 32 + lane;
        if (nb < i1) evn = __ldcs(ev + nb);

        grp_load(evw, 0, xbase, uA, xA);
        grp_load(evw, 1, xbase, uB, xB);
        grp_rmw(accl, uA, xA);
        grp_load(evw, 2, xbase, uA, xA);
        grp_rmw(accl, uB, xB);
        grp_load(evw, 3, xbase, uB, xB);
        grp_rmw(accl, uA, xA);
        grp_rmw(accl, uB, xB);

        evw = evn;
    }
    __syncwarp();

    // flush rows 0..63 (row 64 = pad sink) -> g_partial[slice][p][b], STG only
    float* dst = g_partial + ((size_t)slice * PDIM + bin * 64) * 32 + lane;
    #pragma unroll 4
    for (int row = 0; row < 64; ++row)
        dst[row * 32] = acc[row * ACCSTR + lane];
}

__global__ __launch_bounds__(1024)
void sjlt_reduce(float* __restrict__ out, float scale)
{
    __shared__ float s_r[32 * 33];
    const int tid = threadIdx.x;
    const int p0  = blockIdx.x * 32;

    const int pp = tid >> 5, b = tid & 31;
    const float* src = g_partial + ((size_t)(p0 + pp)) * 32 + b;
    float s = 0.0f;
    #pragma unroll
    for (int c = 0; c < NSLICE; ++c)
        s += src[(size_t)c * (PDIM * 32)];
    s_r[pp * 33 + b] = s * scale;
    __syncthreads();

    const int b2 = tid >> 5, p2 = tid & 31;
    out[(size_t)b2 * PDIM + p0 + p2] = s_r[p2 * 33 + b2];
}

extern "C" void kernel_launch(void* const* d_in, const int* in_sizes, int n_in,
                              void* d_out, int out_size)
{
    const float* x    = (const float*)d_in[0];
    const int4*  idx4 = (const int4*) d_in[1];
    const int4*  sgn4 = (const int4*) d_in[2];

    const int D       = in_sizes[1] / CDIM;            // 1,000,000
    const float scale = 0.35355339059327373f;          // 1/sqrt(8)

    const int packSm = NBIN * PCAP * 4 + NBIN * 4;             // 98,560 B
    const int scatSm = SWPB * ACCSZ * (int)sizeof(float);      // 137,280 B
    cudaFuncSetAttribute(sjlt_pack,
                         cudaFuncAttributeMaxDynamicSharedMemorySize, packSm);
    cudaFuncSetAttribute(sjlt_scatter,
                         cudaFuncAttributeMaxDynamicSharedMemorySize, scatSm);

    sjlt_zero<<<1, NBIN>>>();
    sjlt_transpose<<<D / 64, 256>>>(x, D);
    sjlt_pack<<<(D + PACKD - 1) / PACKD, 256, packSm>>>(idx4, sgn4, D);
    sjlt_scatter<<<NSLICE * 4, SWPB * 32, scatSm>>>();
    sjlt_reduce<<<PDIM / 32, 1024>>>((float*)d_out, scale);
}